// round 17
// baseline (speedup 1.0000x reference)
#include <cuda_runtime.h>
#include <cstdint>
#include <math.h>

#define BMAX   4
#define NN     4096
#define DDIM   1024
#define MSPLIT 128
#define MCHUNK (NN / MSPLIT)     // 32
#define EPSV   1e-6f
#define ROWS_PER_BLOCK 32
#define BATCH  8
#define STAGE_ROWS 2
#define NSTAGES 5                // 5-deep cp.async pipeline (40KB smem)
#define OITER   (ROWS_PER_BLOCK / STAGE_ROWS)  // 16

// Scratch (device globals: no allocation allowed)
__device__ float g_part[BMAX][MSPLIT][3][DDIM]; // partial H0/Hc/Hs (6 MB)
__device__ float g_csp[BMAX][MSPLIT][2];        // partial sum cos / sum sin
__device__ float g_H[BMAX][3][DDIM];            // reduced H0/Hc/Hs
__device__ float g_CS[BMAX][2];                 // final sum cos, sum sin

// Per-batch arrival counters (zero-init; self-reset each launch for graph replay)
__device__ unsigned int g_cnt[BMAX];
__device__ unsigned int g_fold_done[BMAX];

// ---- cp.async helpers (per-thread groups; no block sync needed) -----------
__device__ __forceinline__ void cp_async16(void* smem_dst, const void* gmem_src) {
    unsigned int s = (unsigned int)__cvta_generic_to_shared(smem_dst);
    asm volatile("cp.async.cg.shared.global [%0], [%1], 16;\n" :: "r"(s), "l"(gmem_src));
}
#define CP_COMMIT() asm volatile("cp.async.commit_group;\n" ::: "memory")
#define CP_WAIT4()  asm volatile("cp.async.wait_group 4;\n" ::: "memory")

// ---------------------------------------------------------------------------
// Kernel 1: partial H0/Hc/Hs (reg-batched, MLP=8, __ldcg) + integrated fold.
// grid = (MSPLIT, B) = 512 blocks (single wave -> no deadlock), 256 threads.
// After partials: blocks ms<12 of each batch spin on a per-batch counter
// (48 light pollers, nanosleep backoff) then fold -> g_H in fixed order.
// ---------------------------------------------------------------------------
__global__ void __launch_bounds__(256, 4)
kernel_part(const float* __restrict__ hidden,
            const float* __restrict__ phases) {
    __shared__ float smc[MCHUNK], sms[MCHUNK];
    __shared__ float4 sred[4][64];
    const int b  = blockIdx.y;
    const int ms = blockIdx.x;
    const int m0 = ms * MCHUNK;
    const int t  = threadIdx.x;

    if (t < MCHUNK) {
        float p = phases[b * NN + m0 + t];
        float s, c;
        sincosf(p, &s, &c);
        smc[t] = c;
        sms[t] = s;
        float rc = c, rs = s;
#pragma unroll
        for (int off = 16; off > 0; off >>= 1) {
            rc += __shfl_xor_sync(0xffffffffu, rc, off);
            rs += __shfl_xor_sync(0xffffffffu, rs, off);
        }
        if (t == 0) { g_csp[b][ms][0] = rc; g_csp[b][ms][1] = rs; }
    }
    __syncthreads();

    const float4* hp = (const float4*)(hidden + ((size_t)b * NN + m0) * DDIM) + t;
    float4 a0 = make_float4(0.f, 0.f, 0.f, 0.f);
    float4 ac = a0, as = a0;

    float4 buf[BATCH];
#pragma unroll
    for (int mm = 0; mm < MCHUNK; mm += BATCH) {
#pragma unroll
        for (int i = 0; i < BATCH; ++i)
            buf[i] = __ldcg(&hp[(size_t)(mm + i) * (DDIM / 4)]);  // L2-fill, no L1
#pragma unroll
        for (int i = 0; i < BATCH; ++i) {
            float4 h = buf[i];
            float c = smc[mm + i], s = sms[mm + i];
            a0.x += h.x;               a0.y += h.y;
            a0.z += h.z;               a0.w += h.w;
            ac.x = fmaf(c, h.x, ac.x); ac.y = fmaf(c, h.y, ac.y);
            ac.z = fmaf(c, h.z, ac.z); ac.w = fmaf(c, h.w, ac.w);
            as.x = fmaf(s, h.x, as.x); as.y = fmaf(s, h.y, as.y);
            as.z = fmaf(s, h.z, as.z); as.w = fmaf(s, h.w, as.w);
        }
    }
    __stcg(&((float4*)g_part[b][ms][0])[t], a0);
    __stcg(&((float4*)g_part[b][ms][1])[t], ac);
    __stcg(&((float4*)g_part[b][ms][2])[t], as);

    // ---- signal this batch's partials are published ----
    __threadfence();
    __syncthreads();
    if (t == 0) atomicAdd(&g_cnt[b], 1u);

    if (ms >= 12) return;        // non-folder blocks done

    // ---- folder blocks: wait for all MSPLIT partials of batch b ----
    if (t == 0) {
        while (atomicAdd(&g_cnt[b], 0u) < (unsigned)MSPLIT) __nanosleep(128);
    }
    __syncthreads();

    const int comp = ms >> 2;                 // 0..2
    const int q    = ms & 3;                  // d-quarter
    const int col  = q * 64 + (t & 63);
    const int fs   = t >> 6;                  // 0..3 fold slice

    if (ms == 0 && t < 64) {
        int which = t >> 5;
        int lane  = t & 31;
        float v = 0.f;
#pragma unroll
        for (int i = 0; i < MSPLIT / 32; ++i)
            v += __ldcg(&g_csp[b][lane + i * 32][which]);
#pragma unroll
        for (int off = 16; off > 0; off >>= 1)
            v += __shfl_xor_sync(0xffffffffu, v, off, 32);
        if (lane == 0) g_CS[b][which] = v;
    }

    float4 acc = make_float4(0.f, 0.f, 0.f, 0.f);
    float4 fbuf[BATCH];
    const int ms0 = fs * (MSPLIT / 4);
#pragma unroll
    for (int mm = 0; mm < MSPLIT / 4; mm += BATCH) {
#pragma unroll
        for (int i = 0; i < BATCH; ++i)
            fbuf[i] = __ldcg(&((const float4*)g_part[b][ms0 + mm + i][comp])[col]);
#pragma unroll
        for (int i = 0; i < BATCH; ++i) {
            acc.x += fbuf[i].x; acc.y += fbuf[i].y;
            acc.z += fbuf[i].z; acc.w += fbuf[i].w;
        }
    }
    if (fs != 0) sred[fs][t & 63] = acc;
    __syncthreads();
    if (t < 64) {
#pragma unroll
        for (int i = 1; i < 4; ++i) {
            float4 v = sred[i][t];
            acc.x += v.x; acc.y += v.y; acc.z += v.z; acc.w += v.w;
        }
        ((float4*)g_H[b][comp])[col] = acc;
    }

    // ---- reset counters for next graph replay (folder 0 of each batch) ----
    __threadfence();
    __syncthreads();
    if (t == 0) {
        atomicAdd(&g_fold_done[b], 1u);
        if (ms == 0) {
            while (atomicAdd(&g_fold_done[b], 0u) < 12u) __nanosleep(128);
            g_cnt[b] = 0u;
            g_fold_done[b] = 0u;
            __threadfence();
        }
    }
}

// ---------------------------------------------------------------------------
// Kernel 2 (measured best): output pass — 5-stage cp.async pipeline, FMA,
// evict-first stores. grid = (NN/32, B) = 512 blocks (single wave), 256 thr.
// ---------------------------------------------------------------------------
__global__ void __launch_bounds__(256)
kernel_out(const float* __restrict__ hidden,
           const float* __restrict__ phases,
           const float* __restrict__ alpha_p,
           float* __restrict__ out) {
    __shared__ float4 sbuf[NSTAGES][STAGE_ROWS][256];
    __shared__ float scn[ROWS_PER_BLOCK], ssn[ROWS_PER_BLOCK], scf[ROWS_PER_BLOCK];
    const int b  = blockIdx.y;
    const int n0 = blockIdx.x * ROWS_PER_BLOCK;
    const int t  = threadIdx.x;

    const float a    = fminf(fmaxf(alpha_p[0], 0.f), 1.f);
    const float beta = 1.f - a;

    if (t < ROWS_PER_BLOCK) {
        float p = phases[b * NN + n0 + t];
        float sn, cn;
        sincosf(p, &sn, &cn);
        float C = g_CS[b][0], S = g_CS[b][1];
        float den = fmaxf(0.5f * ((float)NN + fmaf(cn, C, sn * S)), EPSV);
        scn[t] = cn;
        ssn[t] = sn;
        scf[t] = a * 0.5f / den;
    }
    __syncthreads();

    const float4 H0 = ((const float4*)g_H[b][0])[t];
    const float4 Hc = ((const float4*)g_H[b][1])[t];
    const float4 Hs = ((const float4*)g_H[b][2])[t];

    const float4* hv = (const float4*)(hidden + ((size_t)b * NN + n0) * DDIM) + t;
    float4*       ov = (float4*)(out + ((size_t)b * NN + n0) * DDIM) + t;

    // prologue: stages 0..NSTAGES-2
#pragma unroll
    for (int s = 0; s < NSTAGES - 1; ++s) {
#pragma unroll
        for (int r = 0; r < STAGE_ROWS; ++r)
            cp_async16(&sbuf[s][r][t], hv + (size_t)(s * STAGE_ROWS + r) * (DDIM / 4));
        CP_COMMIT();
    }

#pragma unroll
    for (int it = 0; it < OITER; ++it) {
        const int nxt = it + NSTAGES - 1;
        if (nxt < OITER) {
#pragma unroll
            for (int r = 0; r < STAGE_ROWS; ++r)
                cp_async16(&sbuf[nxt % NSTAGES][r][t],
                           hv + (size_t)(nxt * STAGE_ROWS + r) * (DDIM / 4));
        }
        CP_COMMIT();
        CP_WAIT4();
#pragma unroll
        for (int r = 0; r < STAGE_ROWS; ++r) {
            int row = it * STAGE_ROWS + r;
            float cn = scn[row], sn = ssn[row], cf = scf[row];
            float4 h = sbuf[it % NSTAGES][r][t];
            float4 o;
            o.x = fmaf(cf, fmaf(sn, Hs.x, fmaf(cn, Hc.x, H0.x)), beta * h.x);
            o.y = fmaf(cf, fmaf(sn, Hs.y, fmaf(cn, Hc.y, H0.y)), beta * h.y);
            o.z = fmaf(cf, fmaf(sn, Hs.z, fmaf(cn, Hc.z, H0.z)), beta * h.z);
            o.w = fmaf(cf, fmaf(sn, Hs.w, fmaf(cn, Hc.w, H0.w)), beta * h.w);
            __stcs(&ov[(size_t)row * (DDIM / 4)], o);  // evict-first
        }
    }
}

// ---------------------------------------------------------------------------
// Launch — 2 kernels (fold integrated into kernel_part's tail).
// ---------------------------------------------------------------------------
extern "C" void kernel_launch(void* const* d_in, const int* in_sizes, int n_in,
                              void* d_out, int out_size) {
    const float* hidden = (const float*)d_in[0];
    const float* phases = (const float*)d_in[1];
    const float* alpha  = (const float*)d_in[2];
    float* out = (float*)d_out;

    const int B = in_sizes[1] / NN;

    kernel_part<<<dim3(MSPLIT, B), 256>>>(hidden, phases);
    kernel_out<<<dim3(NN / ROWS_PER_BLOCK, B), 256>>>(hidden, phases, alpha, out);
}